// round 1
// baseline (speedup 1.0000x reference)
#include <cuda_runtime.h>
#include <math.h>

#define BB 64
#define LL 1024
#define DD 256
#define BL (BB * LL)

// Scratch: q and mix for both attentions (alpha=0, beta=1). 4 x 64MB.
__device__ float g_q[2][(size_t)BL * DD];
__device__ float g_mix[2][(size_t)BL * DD];

// ---------------------------------------------------------------------------
// Kernel 1: q projection.  q[m][n] = sum_k X[m][k] * W[n][k]
//   M = BL, N = 256, K = 256. z=0: X=log, W=W_in_alpha ; z=1: X=metrics, W=W_in_beta
// ---------------------------------------------------------------------------
__global__ __launch_bounds__(256) void proj_kernel(
    const float* __restrict__ log_f, const float* __restrict__ met_f,
    const float* __restrict__ Wia,   const float* __restrict__ Wib)
{
    const int z = blockIdx.z;
    const float* X = z ? met_f : log_f;
    const float* W = z ? Wib : Wia;
    float* O = g_q[z];

    __shared__ float Xs[64][36];
    __shared__ float Ws[64][36];

    const int tid = threadIdx.x;
    const int tx = tid & 15;
    const int ty = tid >> 4;
    const int m0 = blockIdx.x * 64;
    const int n0 = blockIdx.y * 64;

    float acc[4][4] = {};

    for (int k0 = 0; k0 < 256; k0 += 32) {
#pragma unroll
        for (int t = 0; t < 2; t++) {
            int idx = tid + t * 256;          // 0..511
            int row = idx >> 3;               // 64 rows, 8 float4 per row
            int c4  = idx & 7;
            float4 v = *(const float4*)(X + (size_t)(m0 + row) * 256 + k0 + c4 * 4);
            *(float4*)&Xs[row][c4 * 4] = v;
            float4 w = *(const float4*)(W + (size_t)(n0 + row) * 256 + k0 + c4 * 4);
            *(float4*)&Ws[row][c4 * 4] = w;
        }
        __syncthreads();
#pragma unroll
        for (int k4 = 0; k4 < 8; k4++) {
            float4 a[4], b[4];
#pragma unroll
            for (int i = 0; i < 4; i++) a[i] = *(float4*)&Xs[ty * 4 + i][k4 * 4];
#pragma unroll
            for (int j = 0; j < 4; j++) b[j] = *(float4*)&Ws[tx + 16 * j][k4 * 4];
#pragma unroll
            for (int i = 0; i < 4; i++)
#pragma unroll
                for (int j = 0; j < 4; j++)
                    acc[i][j] += a[i].x * b[j].x + a[i].y * b[j].y +
                                 a[i].z * b[j].z + a[i].w * b[j].w;
        }
        __syncthreads();
    }
#pragma unroll
    for (int i = 0; i < 4; i++)
#pragma unroll
        for (int j = 0; j < 4; j++)
            O[(size_t)(m0 + ty * 4 + i) * 256 + n0 + tx + 16 * j] = acc[i][j];
}

// ---------------------------------------------------------------------------
// Kernel 2: flash-style cross attention.
//   z=0: query-side q = g_q[0] (from log), context = metrics
//   z=1: query-side q = g_q[1] (from metrics), context = log
//   produces mix = softmax(q @ ctx^T) @ ctx into g_mix[z]
// ---------------------------------------------------------------------------
#define CSTR 260   // padded smem row stride for Q/C tiles (256 + 4)
#define PSTR 65    // padded smem row stride for P tile

__global__ __launch_bounds__(256) void attn_kernel(
    const float* __restrict__ log_f, const float* __restrict__ met_f)
{
    extern __shared__ float sm[];
    float* Qs = sm;                         // 64 * 260
    float* Cs = sm + 64 * CSTR;             // 64 * 260
    float* Ps = sm + 2 * 64 * CSTR;         // 64 * 65

    const int z  = blockIdx.z;
    const int b  = blockIdx.y;
    const int l0 = blockIdx.x * 64;
    const float* ctx  = z ? log_f : met_f;
    const float* qg   = g_q[z];
    float*       mixg = g_mix[z];

    const int tid = threadIdx.x;
    const int tx = tid & 15;
    const int ty = tid >> 4;

    // Load Q tile: 64 rows x 256 cols
#pragma unroll
    for (int t = 0; t < 16; t++) {
        int idx = tid + t * 256;            // 0..4095 (float4 index)
        int row = idx >> 6;
        int c4  = idx & 63;
        float4 v = *(const float4*)(qg + ((size_t)b * LL + l0 + row) * 256 + c4 * 4);
        *(float4*)&Qs[row * CSTR + c4 * 4] = v;
    }

    float acc[4][16] = {};
    float mrow[4], lrow[4];
#pragma unroll
    for (int i = 0; i < 4; i++) { mrow[i] = -1e30f; lrow[i] = 0.f; }

    for (int s0 = 0; s0 < LL; s0 += 64) {
        // Load context tile: 64 rows x 256
#pragma unroll
        for (int t = 0; t < 16; t++) {
            int idx = tid + t * 256;
            int row = idx >> 6;
            int c4  = idx & 63;
            float4 v = *(const float4*)(ctx + ((size_t)b * LL + s0 + row) * 256 + c4 * 4);
            *(float4*)&Cs[row * CSTR + c4 * 4] = v;
        }
        __syncthreads();

        // Scores: sc[i][j] = Q[ty*4+i] . C[tx+16j]   (64x64 tile)
        float sc[4][4] = {};
#pragma unroll 4
        for (int d4 = 0; d4 < 64; d4++) {
            float4 a[4], cb[4];
#pragma unroll
            for (int i = 0; i < 4; i++) a[i]  = *(float4*)&Qs[(ty * 4 + i) * CSTR + d4 * 4];
#pragma unroll
            for (int j = 0; j < 4; j++) cb[j] = *(float4*)&Cs[(tx + 16 * j) * CSTR + d4 * 4];
#pragma unroll
            for (int i = 0; i < 4; i++)
#pragma unroll
                for (int j = 0; j < 4; j++)
                    sc[i][j] += a[i].x * cb[j].x + a[i].y * cb[j].y +
                                a[i].z * cb[j].z + a[i].w * cb[j].w;
        }

        // Online softmax update per owned row
#pragma unroll
        for (int i = 0; i < 4; i++) {
            float tmax = fmaxf(fmaxf(sc[i][0], sc[i][1]), fmaxf(sc[i][2], sc[i][3]));
#pragma unroll
            for (int m = 1; m < 16; m <<= 1)
                tmax = fmaxf(tmax, __shfl_xor_sync(0xffffffffu, tmax, m));
            float mnew  = fmaxf(mrow[i], tmax);
            float scale = __expf(mrow[i] - mnew);
            float rs = 0.f;
            float p[4];
#pragma unroll
            for (int j = 0; j < 4; j++) { p[j] = __expf(sc[i][j] - mnew); rs += p[j]; }
#pragma unroll
            for (int m = 1; m < 16; m <<= 1)
                rs += __shfl_xor_sync(0xffffffffu, rs, m);
            lrow[i] = lrow[i] * scale + rs;
            mrow[i] = mnew;
#pragma unroll
            for (int jj = 0; jj < 16; jj++) acc[i][jj] *= scale;
#pragma unroll
            for (int j = 0; j < 4; j++)
                Ps[(ty * 4 + i) * PSTR + tx + 16 * j] = p[j];
        }
        __syncthreads();

        // acc += P(64x64) @ C(64x256); thread cols n = tx*4 + 64*jj + e
#pragma unroll 4
        for (int k = 0; k < 64; k++) {
            float pv[4];
#pragma unroll
            for (int i = 0; i < 4; i++) pv[i] = Ps[(ty * 4 + i) * PSTR + k];
            float4 cv[4];
#pragma unroll
            for (int jj = 0; jj < 4; jj++)
                cv[jj] = *(float4*)&Cs[k * CSTR + tx * 4 + 64 * jj];
#pragma unroll
            for (int i = 0; i < 4; i++)
#pragma unroll
                for (int jj = 0; jj < 4; jj++) {
                    acc[i][jj * 4 + 0] += pv[i] * cv[jj].x;
                    acc[i][jj * 4 + 1] += pv[i] * cv[jj].y;
                    acc[i][jj * 4 + 2] += pv[i] * cv[jj].z;
                    acc[i][jj * 4 + 3] += pv[i] * cv[jj].w;
                }
        }
        __syncthreads();
    }

    // Normalize and store mix
#pragma unroll
    for (int i = 0; i < 4; i++) {
        float inv = 1.f / lrow[i];
#pragma unroll
        for (int jj = 0; jj < 4; jj++) {
            float4 o;
            o.x = acc[i][jj * 4 + 0] * inv;
            o.y = acc[i][jj * 4 + 1] * inv;
            o.z = acc[i][jj * 4 + 2] * inv;
            o.w = acc[i][jj * 4 + 3] * inv;
            *(float4*)(mixg + ((size_t)b * LL + l0 + ty * 4 + i) * 256 + tx * 4 + 64 * jj) = o;
        }
    }
}

// ---------------------------------------------------------------------------
// Kernel 3: out[m][n] = tanh( sum_{k<512} combined[m][k] * W_out[n][k] )
//   combined = [mix (k<256) | q (k>=256)].  Writes directly into [B, 2L, D] output.
// ---------------------------------------------------------------------------
__global__ __launch_bounds__(256) void out_kernel(
    const float* __restrict__ Woa, const float* __restrict__ Wob,
    float* __restrict__ out)
{
    const int z = blockIdx.z;
    const float* W    = z ? Wob : Woa;
    const float* mixp = g_mix[z];
    const float* qp   = g_q[z];

    __shared__ float Xs[64][36];
    __shared__ float Ws[64][36];

    const int tid = threadIdx.x;
    const int tx = tid & 15;
    const int ty = tid >> 4;
    const int m0 = blockIdx.x * 64;
    const int n0 = blockIdx.y * 64;

    float acc[4][4] = {};

    for (int k0 = 0; k0 < 512; k0 += 32) {
        const float* base = (k0 < 256) ? mixp : qp;
        const int kk = (k0 < 256) ? k0 : (k0 - 256);
#pragma unroll
        for (int t = 0; t < 2; t++) {
            int idx = tid + t * 256;
            int row = idx >> 3;
            int c4  = idx & 7;
            float4 v = *(const float4*)(base + (size_t)(m0 + row) * 256 + kk + c4 * 4);
            *(float4*)&Xs[row][c4 * 4] = v;
            float4 w = *(const float4*)(W + (size_t)(n0 + row) * 512 + k0 + c4 * 4);
            *(float4*)&Ws[row][c4 * 4] = w;
        }
        __syncthreads();
#pragma unroll
        for (int k4 = 0; k4 < 8; k4++) {
            float4 a[4], b[4];
#pragma unroll
            for (int i = 0; i < 4; i++) a[i] = *(float4*)&Xs[ty * 4 + i][k4 * 4];
#pragma unroll
            for (int j = 0; j < 4; j++) b[j] = *(float4*)&Ws[tx + 16 * j][k4 * 4];
#pragma unroll
            for (int i = 0; i < 4; i++)
#pragma unroll
                for (int j = 0; j < 4; j++)
                    acc[i][j] += a[i].x * b[j].x + a[i].y * b[j].y +
                                 a[i].z * b[j].z + a[i].w * b[j].w;
        }
        __syncthreads();
    }

#pragma unroll
    for (int i = 0; i < 4; i++) {
        int m = m0 + ty * 4 + i;
        int bb = m >> 10;          // / 1024
        int l  = m & 1023;
        size_t orow = ((size_t)(bb * 2 + z) * 1024 + l) * 256;
#pragma unroll
        for (int j = 0; j < 4; j++)
            out[orow + n0 + tx + 16 * j] = tanhf(acc[i][j]);
    }
}

// ---------------------------------------------------------------------------
extern "C" void kernel_launch(void* const* d_in, const int* in_sizes, int n_in,
                              void* d_out, int out_size)
{
    const float* log_f = (const float*)d_in[0];
    const float* met_f = (const float*)d_in[1];
    const float* Wia   = (const float*)d_in[2];
    const float* Woa   = (const float*)d_in[3];
    const float* Wib   = (const float*)d_in[4];
    const float* Wob   = (const float*)d_in[5];
    float* out = (float*)d_out;

    // q projections for both attentions
    proj_kernel<<<dim3(BL / 64, 4, 2), 256>>>(log_f, met_f, Wia, Wib);

    // flash attention for both attentions
    const int attn_smem = (2 * 64 * CSTR + 64 * PSTR) * (int)sizeof(float);  // ~150 KB
    cudaFuncSetAttribute(attn_kernel, cudaFuncAttributeMaxDynamicSharedMemorySize, attn_smem);
    attn_kernel<<<dim3(LL / 64, BB, 2), 256, attn_smem>>>(log_f, met_f);

    // fused concat + output GEMM + tanh, written straight into d_out
    out_kernel<<<dim3(BL / 64, 4, 2), 256>>>(Woa, Wob, out);
}

// round 2
// speedup vs baseline: 1.2224x; 1.2224x over previous
#include <cuda_runtime.h>
#include <math.h>

#define BB 64
#define LL 1024
#define DD 256
#define BL (BB * LL)

// Scratch: q and mix for both attentions (alpha=0, beta=1). 4 x 64MB.
__device__ float g_q[2][(size_t)BL * DD];
__device__ float g_mix[2][(size_t)BL * DD];

// ---------------------------------------------------------------------------
// Kernel 1: q projection.  q[m][n] = sum_k X[m][k] * W[n][k]
//   128x128 tile, 8x8 microtile (split rows/cols 4+4), k-major smem, prefetch.
// ---------------------------------------------------------------------------
__global__ __launch_bounds__(256, 2) void proj_kernel(
    const float* __restrict__ log_f, const float* __restrict__ met_f,
    const float* __restrict__ Wia,   const float* __restrict__ Wib)
{
    const int z = blockIdx.z;
    const float* X = z ? met_f : log_f;
    const float* W = z ? Wib : Wia;
    float* O = g_q[z];

    __shared__ float Xs[16][132];
    __shared__ float Ws[16][132];

    const int t  = threadIdx.x;
    const int tm = t & 15;
    const int tn = t >> 4;
    const int m0 = blockIdx.x * 128;
    const int n0 = blockIdx.y * 128;

    const int lm = t >> 2;      // 0..63 loader row base
    const int lq = t & 3;       // k-quad 0..3

    float acc[8][8] = {};
    float4 px[2], pw[2];

    // prefetch k-chunk 0
#pragma unroll
    for (int r = 0; r < 2; r++) {
        px[r] = *(const float4*)(X + (size_t)(m0 + lm + 64 * r) * 256 + lq * 4);
        pw[r] = *(const float4*)(W + (size_t)(n0 + lm + 64 * r) * 256 + lq * 4);
    }

    for (int kt = 0; kt < 16; kt++) {
        // store prefetched chunk to smem (k-major)
#pragma unroll
        for (int r = 0; r < 2; r++) {
            int mr = lm + 64 * r;
            Xs[lq * 4 + 0][mr] = px[r].x;
            Xs[lq * 4 + 1][mr] = px[r].y;
            Xs[lq * 4 + 2][mr] = px[r].z;
            Xs[lq * 4 + 3][mr] = px[r].w;
            Ws[lq * 4 + 0][mr] = pw[r].x;
            Ws[lq * 4 + 1][mr] = pw[r].y;
            Ws[lq * 4 + 2][mr] = pw[r].z;
            Ws[lq * 4 + 3][mr] = pw[r].w;
        }
        __syncthreads();

        if (kt < 15) {
            int k0 = (kt + 1) * 16;
#pragma unroll
            for (int r = 0; r < 2; r++) {
                px[r] = *(const float4*)(X + (size_t)(m0 + lm + 64 * r) * 256 + k0 + lq * 4);
                pw[r] = *(const float4*)(W + (size_t)(n0 + lm + 64 * r) * 256 + k0 + lq * 4);
            }
        }

#pragma unroll
        for (int k = 0; k < 16; k++) {
            float4 a0 = *(float4*)&Xs[k][tm * 4];
            float4 a1 = *(float4*)&Xs[k][64 + tm * 4];
            float4 b0 = *(float4*)&Ws[k][tn * 4];
            float4 b1 = *(float4*)&Ws[k][64 + tn * 4];
            float av[8] = {a0.x, a0.y, a0.z, a0.w, a1.x, a1.y, a1.z, a1.w};
            float bv[8] = {b0.x, b0.y, b0.z, b0.w, b1.x, b1.y, b1.z, b1.w};
#pragma unroll
            for (int i = 0; i < 8; i++)
#pragma unroll
                for (int j = 0; j < 8; j++)
                    acc[i][j] += av[i] * bv[j];
        }
        __syncthreads();
    }

#pragma unroll
    for (int i = 0; i < 8; i++) {
        int row = m0 + ((i < 4) ? (tm * 4 + i) : (64 + tm * 4 + i - 4));
#pragma unroll
        for (int h = 0; h < 2; h++) {
            float4 o;
            o.x = acc[i][h * 4 + 0];
            o.y = acc[i][h * 4 + 1];
            o.z = acc[i][h * 4 + 2];
            o.w = acc[i][h * 4 + 3];
            *(float4*)(O + (size_t)row * 256 + n0 + tn * 4 + 64 * h) = o;
        }
    }
}

// ---------------------------------------------------------------------------
// Kernel 2: flash-style cross attention.  BM=64 q rows, BN=128 ctx rows/tile.
//   Swizzled pad-free C tile (128x256), Q tile 64x256, P tile 64x129.
// ---------------------------------------------------------------------------
#define PSTR 129

__global__ __launch_bounds__(256, 1) void attn_kernel(
    const float* __restrict__ log_f, const float* __restrict__ met_f)
{
    extern __shared__ float sm[];
    float* Qs = sm;                         // 64 * 256
    float* Cs = sm + 64 * 256;              // 128 * 256, xor-swizzled
    float* Ps = sm + 64 * 256 + 128 * 256;  // 64 * 129

    const int z  = blockIdx.z;
    const int b  = blockIdx.y;
    const int l0 = blockIdx.x * 64;
    const float* ctx  = z ? log_f : met_f;
    const float* qg   = g_q[z];
    float*       mixg = g_mix[z];

    const int tid = threadIdx.x;
    const int tx = tid & 15;     // ctx-col lane (cols tx + 16j)
    const int ty = tid >> 4;     // q-row group (rows ty*4 + i)
    const int xs = tx & 7;       // swizzle xor for score-phase loads

    // Load Q tile: 64 rows x 256 cols (unswizzled, row stride 256)
#pragma unroll
    for (int t = 0; t < 16; t++) {
        int idx = tid + t * 256;
        int row = idx >> 6;
        int c4  = idx & 63;
        float4 v = *(const float4*)(qg + ((size_t)b * LL + l0 + row) * 256 + c4 * 4);
        *(float4*)&Qs[row * 256 + c4 * 4] = v;
    }

    float acc[4][16] = {};
    float mrow[4], lrow[4];
#pragma unroll
    for (int i = 0; i < 4; i++) { mrow[i] = -1e30f; lrow[i] = 0.f; }

    for (int s0 = 0; s0 < LL; s0 += 128) {
        // Load context tile: 128 rows x 256, xor-swizzled quads within row
#pragma unroll
        for (int t = 0; t < 32; t++) {
            int idx = tid + t * 256;
            int row = idx >> 6;
            int c4  = idx & 63;
            float4 v = *(const float4*)(ctx + ((size_t)b * LL + s0 + row) * 256 + c4 * 4);
            *(float4*)&Cs[row * 256 + ((c4 ^ (row & 7)) << 2)] = v;
        }
        __syncthreads();

        // Scores: sc[i][j] = Q[ty*4+i] . C[tx+16j]   (64 x 128 tile)
        float sc[4][8] = {};
#pragma unroll 8
        for (int d4 = 0; d4 < 64; d4++) {
            const int ds = (d4 ^ xs) << 2;
            float4 a[4];
#pragma unroll
            for (int i = 0; i < 4; i++)
                a[i] = *(float4*)&Qs[(ty * 4 + i) * 256 + d4 * 4];
#pragma unroll
            for (int j = 0; j < 8; j++) {
                float4 cb = *(float4*)&Cs[(tx + 16 * j) * 256 + ds];
#pragma unroll
                for (int i = 0; i < 4; i++)
                    sc[i][j] += a[i].x * cb.x + a[i].y * cb.y +
                                a[i].z * cb.z + a[i].w * cb.w;
            }
        }

        // Online softmax update per owned row (128 cols spread over 16 lanes x 8)
#pragma unroll
        for (int i = 0; i < 4; i++) {
            float tmax = sc[i][0];
#pragma unroll
            for (int j = 1; j < 8; j++) tmax = fmaxf(tmax, sc[i][j]);
#pragma unroll
            for (int m = 1; m < 16; m <<= 1)
                tmax = fmaxf(tmax, __shfl_xor_sync(0xffffffffu, tmax, m));
            float mnew  = fmaxf(mrow[i], tmax);
            float scale = __expf(mrow[i] - mnew);
            float rs = 0.f;
            float p[8];
#pragma unroll
            for (int j = 0; j < 8; j++) { p[j] = __expf(sc[i][j] - mnew); rs += p[j]; }
#pragma unroll
            for (int m = 1; m < 16; m <<= 1)
                rs += __shfl_xor_sync(0xffffffffu, rs, m);
            lrow[i] = lrow[i] * scale + rs;
            mrow[i] = mnew;
#pragma unroll
            for (int jj = 0; jj < 16; jj++) acc[i][jj] *= scale;
#pragma unroll
            for (int j = 0; j < 8; j++)
                Ps[(ty * 4 + i) * PSTR + tx + 16 * j] = p[j];
        }
        __syncthreads();

        // acc += P(64x128) @ C(128x256); thread cols quads q = tx + 16jj
#pragma unroll 2
        for (int k = 0; k < 128; k++) {
            const int xk = k & 7;
            float pv[4];
#pragma unroll
            for (int i = 0; i < 4; i++) pv[i] = Ps[(ty * 4 + i) * PSTR + k];
            float4 cv[4];
#pragma unroll
            for (int jj = 0; jj < 4; jj++)
                cv[jj] = *(float4*)&Cs[k * 256 + (((tx + 16 * jj) ^ xk) << 2)];
#pragma unroll
            for (int i = 0; i < 4; i++)
#pragma unroll
                for (int jj = 0; jj < 4; jj++) {
                    acc[i][jj * 4 + 0] += pv[i] * cv[jj].x;
                    acc[i][jj * 4 + 1] += pv[i] * cv[jj].y;
                    acc[i][jj * 4 + 2] += pv[i] * cv[jj].z;
                    acc[i][jj * 4 + 3] += pv[i] * cv[jj].w;
                }
        }
        __syncthreads();
    }

    // Normalize and store mix (cols = (tx + 16jj)*4 + e = tx*4 + 64jj + e)
#pragma unroll
    for (int i = 0; i < 4; i++) {
        float inv = 1.f / lrow[i];
#pragma unroll
        for (int jj = 0; jj < 4; jj++) {
            float4 o;
            o.x = acc[i][jj * 4 + 0] * inv;
            o.y = acc[i][jj * 4 + 1] * inv;
            o.z = acc[i][jj * 4 + 2] * inv;
            o.w = acc[i][jj * 4 + 3] * inv;
            *(float4*)(mixg + ((size_t)b * LL + l0 + ty * 4 + i) * 256 + tx * 4 + 64 * jj) = o;
        }
    }
}

// ---------------------------------------------------------------------------
// Kernel 3: out[m][n] = tanh( sum_{k<512} combined[m][k] * W_out[n][k] )
//   combined = [mix (k<256) | q (k>=256)].  128x128 tile, 8x8 microtile.
// ---------------------------------------------------------------------------
__global__ __launch_bounds__(256, 2) void out_kernel(
    const float* __restrict__ Woa, const float* __restrict__ Wob,
    float* __restrict__ out)
{
    const int z = blockIdx.z;
    const float* W    = z ? Wob : Woa;
    const float* mixp = g_mix[z];
    const float* qp   = g_q[z];

    __shared__ float Xs[16][132];
    __shared__ float Ws[16][132];

    const int t  = threadIdx.x;
    const int tm = t & 15;
    const int tn = t >> 4;
    const int m0 = blockIdx.x * 128;
    const int n0 = blockIdx.y * 128;

    const int lm = t >> 2;
    const int lq = t & 3;

    float acc[8][8] = {};
    float4 px[2], pw[2];

    // prefetch k-chunk 0 (k < 256 -> mix)
#pragma unroll
    for (int r = 0; r < 2; r++) {
        px[r] = *(const float4*)(mixp + (size_t)(m0 + lm + 64 * r) * 256 + lq * 4);
        pw[r] = *(const float4*)(W + (size_t)(n0 + lm + 64 * r) * 512 + lq * 4);
    }

    for (int kt = 0; kt < 32; kt++) {
#pragma unroll
        for (int r = 0; r < 2; r++) {
            int mr = lm + 64 * r;
            Xs[lq * 4 + 0][mr] = px[r].x;
            Xs[lq * 4 + 1][mr] = px[r].y;
            Xs[lq * 4 + 2][mr] = px[r].z;
            Xs[lq * 4 + 3][mr] = px[r].w;
            Ws[lq * 4 + 0][mr] = pw[r].x;
            Ws[lq * 4 + 1][mr] = pw[r].y;
            Ws[lq * 4 + 2][mr] = pw[r].z;
            Ws[lq * 4 + 3][mr] = pw[r].w;
        }
        __syncthreads();

        if (kt < 31) {
            int k0 = (kt + 1) * 16;
            const float* base = (k0 < 256) ? mixp : qp;
            int kk = (k0 < 256) ? k0 : (k0 - 256);
#pragma unroll
            for (int r = 0; r < 2; r++) {
                px[r] = *(const float4*)(base + (size_t)(m0 + lm + 64 * r) * 256 + kk + lq * 4);
                pw[r] = *(const float4*)(W + (size_t)(n0 + lm + 64 * r) * 512 + k0 + lq * 4);
            }
        }

#pragma unroll
        for (int k = 0; k < 16; k++) {
            float4 a0 = *(float4*)&Xs[k][tm * 4];
            float4 a1 = *(float4*)&Xs[k][64 + tm * 4];
            float4 b0 = *(float4*)&Ws[k][tn * 4];
            float4 b1 = *(float4*)&Ws[k][64 + tn * 4];
            float av[8] = {a0.x, a0.y, a0.z, a0.w, a1.x, a1.y, a1.z, a1.w};
            float bv[8] = {b0.x, b0.y, b0.z, b0.w, b1.x, b1.y, b1.z, b1.w};
#pragma unroll
            for (int i = 0; i < 8; i++)
#pragma unroll
                for (int j = 0; j < 8; j++)
                    acc[i][j] += av[i] * bv[j];
        }
        __syncthreads();
    }

#pragma unroll
    for (int i = 0; i < 8; i++) {
        int m = m0 + ((i < 4) ? (tm * 4 + i) : (64 + tm * 4 + i - 4));
        int bb = m >> 10;
        int l  = m & 1023;
        size_t orow = ((size_t)(bb * 2 + z) * 1024 + l) * 256;
#pragma unroll
        for (int h = 0; h < 2; h++) {
            float4 o;
            o.x = tanhf(acc[i][h * 4 + 0]);
            o.y = tanhf(acc[i][h * 4 + 1]);
            o.z = tanhf(acc[i][h * 4 + 2]);
            o.w = tanhf(acc[i][h * 4 + 3]);
            *(float4*)(out + orow + n0 + tn * 4 + 64 * h) = o;
        }
    }
}

// ---------------------------------------------------------------------------
extern "C" void kernel_launch(void* const* d_in, const int* in_sizes, int n_in,
                              void* d_out, int out_size)
{
    const float* log_f = (const float*)d_in[0];
    const float* met_f = (const float*)d_in[1];
    const float* Wia   = (const float*)d_in[2];
    const float* Woa   = (const float*)d_in[3];
    const float* Wib   = (const float*)d_in[4];
    const float* Wob   = (const float*)d_in[5];
    float* out = (float*)d_out;

    // q projections for both attentions
    proj_kernel<<<dim3(BL / 128, 2, 2), 256>>>(log_f, met_f, Wia, Wib);

    // flash attention for both attentions
    const int attn_smem = (64 * 256 + 128 * 256 + 64 * PSTR) * (int)sizeof(float); // 229632 B
    cudaFuncSetAttribute(attn_kernel, cudaFuncAttributeMaxDynamicSharedMemorySize, attn_smem);
    attn_kernel<<<dim3(LL / 64, BB, 2), 256, attn_smem>>>(log_f, met_f);

    // fused concat + output GEMM + tanh, written straight into d_out
    out_kernel<<<dim3(BL / 128, 2, 2), 256>>>(Woa, Wob, out);
}